// round 15
// baseline (speedup 1.0000x reference)
#include <cuda_runtime.h>
#include <cuda_bf16.h>
#include <math.h>

#define D 128
#define C 64
#define ROWS_PER_TILE 128
#define THREADS_MAIN 512   // 16 warps, each owns 4 classes
#define GRID_MAIN 296      // 2 blocks/SM
#define LAMBDA_PROTO 0.5f

// dynamic smem: logits 2*128*64 f = 65536 B ; labels 2*128 i = 1024 B
#define SMEM_BYTES (65536 + 1024)

// -------- device scratch (zero at module load; last block re-zeroes) --------
__device__ float g_sums[C * D];
__device__ float g_counts[C];
__device__ float g_z2[C];
__device__ float g_ce;
__device__ unsigned int g_done;

#define ACC_ROW(k, xv, inv, z2)                                            \
    do {                                                                   \
        if ((k) == 0) {                                                    \
            a0.x = fmaf((xv).x, (inv), a0.x); a0.y = fmaf((xv).y, (inv), a0.y); \
            a0.z = fmaf((xv).z, (inv), a0.z); a0.w = fmaf((xv).w, (inv), a0.w); \
            c0 += 1.0f; q0 += (z2);                                        \
        } else if ((k) == 1) {                                             \
            a1.x = fmaf((xv).x, (inv), a1.x); a1.y = fmaf((xv).y, (inv), a1.y); \
            a1.z = fmaf((xv).z, (inv), a1.z); a1.w = fmaf((xv).w, (inv), a1.w); \
            c1 += 1.0f; q1 += (z2);                                        \
        } else if ((k) == 2) {                                             \
            a2.x = fmaf((xv).x, (inv), a2.x); a2.y = fmaf((xv).y, (inv), a2.y); \
            a2.z = fmaf((xv).z, (inv), a2.z); a2.w = fmaf((xv).w, (inv), a2.w); \
            c2 += 1.0f; q2 += (z2);                                        \
        } else {                                                           \
            a3.x = fmaf((xv).x, (inv), a3.x); a3.y = fmaf((xv).y, (inv), a3.y); \
            a3.z = fmaf((xv).z, (inv), a3.z); a3.w = fmaf((xv).w, (inv), a3.w); \
            c3 += 1.0f; q3 += (z2);                                        \
        }                                                                  \
    } while (0)

// ---------------------------------------------------------
__global__ __launch_bounds__(THREADS_MAIN, 2)
void fused_kernel(const float* __restrict__ emb,
                  const float* __restrict__ logits,
                  const unsigned int* __restrict__ lab_w, int N,
                  float* __restrict__ out)
{
    extern __shared__ float smem[];
    float* lg_s = smem;                               // [2][128*64]
    int*   lb_s = (int*)(smem + 2 * ROWS_PER_TILE * C); // [2][128]

    __shared__ float s_red[16];
    __shared__ float s_pc[2 * C];
    __shared__ unsigned int s_rank;

    const int tid  = threadIdx.x;
    const int wid  = tid >> 5;
    const int lane = tid & 31;
    const int base = wid * 4;          // warp owns classes [base, base+4)
    const int half = lane >> 4;        // CE: half-warp id
    const int hl   = lane & 15;        // CE: lane within half

    // --- per-warp label dtype detection ---
    unsigned probe = lab_w[2 * lane + 1];
    const int lsh = (__ballot_sync(0xffffffffu, probe != 0u) == 0u) ? 1 : 0;

    float4 a0 = {0,0,0,0}, a1 = a0, a2 = a0, a3 = a0;
    float  c0 = 0, c1 = 0, c2 = 0, c3 = 0;
    float  q0 = 0, q1 = 0, q2 = 0, q3 = 0;
    float  ce_acc = 0.0f;

    const float4* emb4 = (const float4*)emb;
    const float4* lg4  = (const float4*)logits;
    const int ntiles = (N + ROWS_PER_TILE - 1) / ROWS_PER_TILE;

    const unsigned lg_s_base = (unsigned)__cvta_generic_to_shared(lg_s);
    const unsigned lb_s_base = (unsigned)__cvta_generic_to_shared(lb_s);

    // ---- staging helper (cp.async; no register live-ranges) ----
    auto stage = [&](int t, int p) {
        if (t >= ntiles) return;
        const int row0 = t * ROWS_PER_TILE;
        const float4* src = lg4 + (size_t)row0 * (C / 4);
        unsigned dst = lg_s_base + (unsigned)p * (ROWS_PER_TILE * C * 4);
        #pragma unroll
        for (int k = 0; k < 4; ++k) {
            int i = tid + k * THREADS_MAIN;          // 2048 float4 per tile
            if (row0 + (i >> 4) < N) {
                asm volatile("cp.async.cg.shared.global [%0], [%1], 16;\n"
                             :: "r"(dst + (unsigned)i * 16), "l"(src + i));
            }
        }
        if (tid < ROWS_PER_TILE) {
            int r = row0 + tid;
            if (r < N) {
                const unsigned int* ls = lab_w + ((unsigned)r << lsh);
                unsigned dl = lb_s_base + (unsigned)p * (ROWS_PER_TILE * 4)
                            + (unsigned)tid * 4;
                asm volatile("cp.async.ca.shared.global [%0], [%1], 4;\n"
                             :: "r"(dl), "l"(ls));
            }
        }
    };

    // ---- initial prefetch ----
    stage(blockIdx.x, 0);
    asm volatile("cp.async.commit_group;\n" ::: "memory");

    int parity = 0;
    for (int tile = blockIdx.x; tile < ntiles; tile += GRID_MAIN) {
        // prefetch next tile into other buffer (fully read by trailing sync)
        stage(tile + GRID_MAIN, parity ^ 1);
        asm volatile("cp.async.commit_group;\n" ::: "memory");
        asm volatile("cp.async.wait_group 1;\n" ::: "memory");
        __syncthreads();

        const int row0 = tile * ROWS_PER_TILE;
        const float* lgp = lg_s + parity * (ROWS_PER_TILE * C);
        const int*   lbp = lb_s + parity * ROWS_PER_TILE;

        // ---- proto: ballot ownership (labels from smem) ----
        unsigned long long m128[2];
        {
            unsigned b[4];
            #pragma unroll
            for (int h = 0; h < 4; ++h) {
                int li = lane + 32 * h;
                int lv = lbp[li];
                b[h] = __ballot_sync(0xffffffffu,
                                     (row0 + li < N) && ((unsigned)(lv - base) < 4u));
            }
            m128[0] = (unsigned long long)b[0] | ((unsigned long long)b[1] << 32);
            m128[1] = (unsigned long long)b[2] | ((unsigned long long)b[3] << 32);
        }

        // ---- matched rows, four-at-a-time; joint 4-row reduction ----
        #pragma unroll
        for (int part = 0; part < 2; ++part) {
            unsigned long long m = m128[part];
            const int lbase = part * 64;
            while (m) {
                int nb = 0;
                int li[4];
                #pragma unroll
                for (int j = 0; j < 4; ++j) {
                    if (m) {
                        li[j] = lbase + (int)(__ffsll((long long)m) - 1);
                        m &= m - 1;
                        nb = j + 1;
                    } else {
                        li[j] = li[0];
                    }
                }
                int kk[4];
                float4 x[4];
                #pragma unroll
                for (int j = 0; j < 4; ++j) {
                    kk[j] = lbp[li[j]] - base;                        // LDS bcast
                    x[j]  = emb4[(unsigned)((row0 + li[j]) * (D / 4) + lane)];
                }
                float s[4];
                #pragma unroll
                for (int j = 0; j < 4; ++j)
                    s[j] = x[j].x*x[j].x + x[j].y*x[j].y + x[j].z*x[j].z + x[j].w*x[j].w;
                #pragma unroll
                for (int j = 0; j < 4; ++j) s[j] += __shfl_xor_sync(0xffffffffu, s[j], 16);
                #pragma unroll
                for (int j = 0; j < 4; ++j) s[j] += __shfl_xor_sync(0xffffffffu, s[j], 8);
                int g = lane >> 3;
                float t = (g & 2) ? ((g & 1) ? s[3] : s[2])
                                  : ((g & 1) ? s[1] : s[0]);
                t += __shfl_xor_sync(0xffffffffu, t, 4);
                t += __shfl_xor_sync(0xffffffffu, t, 2);
                t += __shfl_xor_sync(0xffffffffu, t, 1);
                s[0] = __shfl_sync(0xffffffffu, t, 0);
                s[1] = __shfl_sync(0xffffffffu, t, 8);
                s[2] = __shfl_sync(0xffffffffu, t, 16);
                s[3] = __shfl_sync(0xffffffffu, t, 24);
                #pragma unroll
                for (int j = 0; j < 4; ++j) {
                    if (j < nb) {
                        float inv = rsqrtf(fmaxf(s[j], 1e-24f)); // ==1/max(||x||,1e-12)
                        float z2  = s[j] * inv * inv;
                        ACC_ROW(kk[j], x[j], inv, z2);
                    }
                }
            }
        }

        // ---- CE: half-warp per row, everything from smem ----
        {
            float4 v[4]; float gt[4]; bool has[4];
            #pragma unroll
            for (int u = 0; u < 4; ++u) {
                int lr = wid * 8 + u * 2 + half;          // local row 0..127
                has[u] = row0 + lr < N;
                v[u] = ((const float4*)lgp)[(unsigned)(lr * (C / 4) + hl)];
                int l = lbp[lr];
                gt[u] = lgp[(unsigned)(lr * C + (l & 63))];
            }
            float e[4];
            #pragma unroll
            for (int u = 0; u < 4; ++u)
                e[u] = __expf(v[u].x) + __expf(v[u].y)
                     + __expf(v[u].z) + __expf(v[u].w);
            #pragma unroll
            for (int o = 8; o; o >>= 1) {
                #pragma unroll
                for (int u = 0; u < 4; ++u)
                    e[u] += __shfl_xor_sync(0xffffffffu, e[u], o);
            }
            if (hl == 0) {
                #pragma unroll
                for (int u = 0; u < 4; ++u)
                    if (has[u]) ce_acc += __logf(e[u]) - gt[u];
            }
        }

        __syncthreads();   // all reads of buf[parity] done before it's re-staged
        parity ^= 1;
    }

    // ---- flush per-class accumulators (one-shot) ----
    const int dbase = lane * 4;
    atomicAdd(&g_sums[(base + 0) * D + dbase + 0], a0.x);
    atomicAdd(&g_sums[(base + 0) * D + dbase + 1], a0.y);
    atomicAdd(&g_sums[(base + 0) * D + dbase + 2], a0.z);
    atomicAdd(&g_sums[(base + 0) * D + dbase + 3], a0.w);
    atomicAdd(&g_sums[(base + 1) * D + dbase + 0], a1.x);
    atomicAdd(&g_sums[(base + 1) * D + dbase + 1], a1.y);
    atomicAdd(&g_sums[(base + 1) * D + dbase + 2], a1.z);
    atomicAdd(&g_sums[(base + 1) * D + dbase + 3], a1.w);
    atomicAdd(&g_sums[(base + 2) * D + dbase + 0], a2.x);
    atomicAdd(&g_sums[(base + 2) * D + dbase + 1], a2.y);
    atomicAdd(&g_sums[(base + 2) * D + dbase + 2], a2.z);
    atomicAdd(&g_sums[(base + 2) * D + dbase + 3], a2.w);
    atomicAdd(&g_sums[(base + 3) * D + dbase + 0], a3.x);
    atomicAdd(&g_sums[(base + 3) * D + dbase + 1], a3.y);
    atomicAdd(&g_sums[(base + 3) * D + dbase + 2], a3.z);
    atomicAdd(&g_sums[(base + 3) * D + dbase + 3], a3.w);
    if (lane == 0) {
        atomicAdd(&g_counts[base + 0], c0); atomicAdd(&g_z2[base + 0], q0);
        atomicAdd(&g_counts[base + 1], c1); atomicAdd(&g_z2[base + 1], q1);
        atomicAdd(&g_counts[base + 2], c2); atomicAdd(&g_z2[base + 2], q2);
        atomicAdd(&g_counts[base + 3], c3); atomicAdd(&g_z2[base + 3], q3);
    }

    // ---- block CE reduce (lanes 0 and 16 hold partials) ----
    ce_acc += __shfl_xor_sync(0xffffffffu, ce_acc, 16);
    if (lane == 0) s_red[wid] = ce_acc;
    __syncthreads();
    if (tid == 0) {
        float s = 0.0f;
        #pragma unroll
        for (int i = 0; i < THREADS_MAIN / 32; ++i) s += s_red[i];
        atomicAdd(&g_ce, s);
        __threadfence();
        s_rank = atomicAdd(&g_done, 1u);
    }
    __syncthreads();

    // =========== last block: finalize + re-zero scratch ===========
    if (s_rank == GRID_MAIN - 1) {
        __threadfence();

        #pragma unroll
        for (int cc = 0; cc < 4; ++cc) {
            int c = base + cc;
            float4 vv = ((const float4*)(g_sums + c * D))[lane];
            float dot = vv.x*vv.x + vv.y*vv.y + vv.z*vv.z + vv.w*vv.w;
            #pragma unroll
            for (int o = 16; o; o >>= 1)
                dot += __shfl_xor_sync(0xffffffffu, dot, o);
            if (lane == 0) {
                float cnt  = g_counts[c];
                float safe = fmaxf(cnt, 1.0f);
                float ssd  = g_z2[c] - dot / safe;
                bool valid = (cnt > 1.0f);
                s_pc[c]     = valid ? (ssd / safe) : 0.0f;
                s_pc[C + c] = valid ? 1.0f : 0.0f;
            }
        }
        __syncthreads();
        if (tid == 0) {
            float sp = 0.0f, nv = 0.0f;
            #pragma unroll
            for (int c = 0; c < C; ++c) { sp += s_pc[c]; nv += s_pc[C + c]; }
            float proto = sp / fmaxf(nv, 1.0f);
            float ce    = g_ce / (float)N;
            out[0] = (1.0f - LAMBDA_PROTO) * ce + LAMBDA_PROTO * proto;
        }

        for (int i = tid; i < C * D; i += THREADS_MAIN) g_sums[i] = 0.0f;
        if (tid < C) { g_counts[tid] = 0.0f; g_z2[tid] = 0.0f; }
        if (tid == 0) { g_ce = 0.0f; __threadfence(); g_done = 0u; }
    }
}

// ---------------------------------------------------------
extern "C" void kernel_launch(void* const* d_in, const int* in_sizes, int n_in,
                              void* d_out, int out_size) {
    const float* emb          = (const float*)d_in[0];
    const float* logits       = (const float*)d_in[1];
    const unsigned int* lab_w = (const unsigned int*)d_in[2];
    int N = in_sizes[2];

    cudaFuncSetAttribute(fused_kernel,
                         cudaFuncAttributeMaxDynamicSharedMemorySize, SMEM_BYTES);

    fused_kernel<<<GRID_MAIN, THREADS_MAIN, SMEM_BYTES>>>(
        emb, logits, lab_w, N, (float*)d_out);
}

// round 16
// speedup vs baseline: 1.1341x; 1.1341x over previous
#include <cuda_runtime.h>
#include <cuda_bf16.h>
#include <math.h>

#define D 128
#define C 64
#define THREADS_MAIN 512   // 16 warps
#define GRID_MAIN 296      // 2 blocks/SM; %3==2 -> CE role (98), else proto (198)
#define NPROTO 198
#define NCE 98
#define LAMBDA_PROTO 0.5f

// -------- device scratch (zero at module load; last block re-zeroes) --------
__device__ float g_sums[C * D];
__device__ float g_counts[C];
__device__ float g_ce;
__device__ unsigned int g_done;

#define ACC_ROW(k, xv, inv)                                                \
    do {                                                                   \
        if ((k) == 0) {                                                    \
            a0.x = fmaf((xv).x, (inv), a0.x); a0.y = fmaf((xv).y, (inv), a0.y); \
            a0.z = fmaf((xv).z, (inv), a0.z); a0.w = fmaf((xv).w, (inv), a0.w); \
            c0 += 1.0f;                                                    \
        } else if ((k) == 1) {                                             \
            a1.x = fmaf((xv).x, (inv), a1.x); a1.y = fmaf((xv).y, (inv), a1.y); \
            a1.z = fmaf((xv).z, (inv), a1.z); a1.w = fmaf((xv).w, (inv), a1.w); \
            c1 += 1.0f;                                                    \
        } else if ((k) == 2) {                                             \
            a2.x = fmaf((xv).x, (inv), a2.x); a2.y = fmaf((xv).y, (inv), a2.y); \
            a2.z = fmaf((xv).z, (inv), a2.z); a2.w = fmaf((xv).w, (inv), a2.w); \
            c2 += 1.0f;                                                    \
        } else {                                                           \
            a3.x = fmaf((xv).x, (inv), a3.x); a3.y = fmaf((xv).y, (inv), a3.y); \
            a3.z = fmaf((xv).z, (inv), a3.z); a3.w = fmaf((xv).w, (inv), a3.w); \
            c3 += 1.0f;                                                    \
        }                                                                  \
    } while (0)

// ---------------------------------------------------------
__global__ __launch_bounds__(THREADS_MAIN, 2)
void fused_kernel(const float* __restrict__ emb,
                  const float* __restrict__ logits,
                  const unsigned int* __restrict__ lab_w, int N,
                  float* __restrict__ out)
{
    __shared__ float s_red[16];
    __shared__ float s_pc[2 * C];
    __shared__ unsigned int s_rank;

    const int tid  = threadIdx.x;
    const int wid  = tid >> 5;
    const int lane = tid & 31;
    const int base = wid * 4;          // proto: warp owns classes [base, base+4)
    const int half = lane >> 4;        // CE: half-warp id
    const int hl   = lane & 15;        // CE: lane within half

    // --- per-warp label dtype detection ---
    unsigned probe = lab_w[2 * lane + 1];
    const int lsh = (__ballot_sync(0xffffffffu, probe != 0u) == 0u) ? 1 : 0;

    float ce_acc = 0.0f;
    const int role_ce = ((blockIdx.x % 3) == 2);

    if (!role_ce) {
        // ================= PROTO role (198 blocks) =================
        float4 a0 = {0,0,0,0}, a1 = a0, a2 = a0, a3 = a0;
        float  c0 = 0, c1 = 0, c2 = 0, c3 = 0;

        const float4* emb4 = (const float4*)emb;
        const int pid = (blockIdx.x / 3) * 2 + (blockIdx.x % 3);  // 0..197
        const int ntiles = (N + 127) / 128;

        for (int tile = pid; tile < ntiles; tile += NPROTO) {
            const int row0 = tile * 128;

            unsigned long long m128[2];
            {
                unsigned b[4];
                #pragma unroll
                for (int h = 0; h < 4; ++h) {
                    int r = row0 + lane + 32 * h;
                    int lv = (r < N) ? (int)lab_w[(unsigned)(r << lsh)] : -1;
                    b[h] = __ballot_sync(0xffffffffu, (unsigned)(lv - base) < 4u);
                }
                m128[0] = (unsigned long long)b[0] | ((unsigned long long)b[1] << 32);
                m128[1] = (unsigned long long)b[2] | ((unsigned long long)b[3] << 32);
            }

            #pragma unroll
            for (int part = 0; part < 2; ++part) {
                unsigned long long m = m128[part];
                const int pbase = row0 + part * 64;
                while (m) {
                    int nb = 0;
                    int r[4];
                    #pragma unroll
                    for (int j = 0; j < 4; ++j) {
                        if (m) {
                            r[j] = pbase + (int)(__ffsll((long long)m) - 1);
                            m &= m - 1;
                            nb = j + 1;
                        } else {
                            r[j] = r[0];
                        }
                    }
                    int kk[4];
                    float4 x[4];
                    #pragma unroll
                    for (int j = 0; j < 4; ++j) {
                        kk[j] = (int)lab_w[(unsigned)(r[j] << lsh)] - base; // bcast
                        x[j]  = emb4[(unsigned)(r[j] * (D / 4) + lane)];
                    }
                    float s[4];
                    #pragma unroll
                    for (int j = 0; j < 4; ++j)
                        s[j] = x[j].x*x[j].x + x[j].y*x[j].y
                             + x[j].z*x[j].z + x[j].w*x[j].w;
                    #pragma unroll
                    for (int j = 0; j < 4; ++j)
                        s[j] += __shfl_xor_sync(0xffffffffu, s[j], 16);
                    #pragma unroll
                    for (int j = 0; j < 4; ++j)
                        s[j] += __shfl_xor_sync(0xffffffffu, s[j], 8);
                    int g = lane >> 3;
                    float t = (g & 2) ? ((g & 1) ? s[3] : s[2])
                                      : ((g & 1) ? s[1] : s[0]);
                    t += __shfl_xor_sync(0xffffffffu, t, 4);
                    t += __shfl_xor_sync(0xffffffffu, t, 2);
                    t += __shfl_xor_sync(0xffffffffu, t, 1);
                    s[0] = __shfl_sync(0xffffffffu, t, 0);
                    s[1] = __shfl_sync(0xffffffffu, t, 8);
                    s[2] = __shfl_sync(0xffffffffu, t, 16);
                    s[3] = __shfl_sync(0xffffffffu, t, 24);
                    #pragma unroll
                    for (int j = 0; j < 4; ++j) {
                        if (j < nb) {
                            float inv = rsqrtf(fmaxf(s[j], 1e-24f)); // ==1/max(||x||,1e-12)
                            ACC_ROW(kk[j], x[j], inv);
                        }
                    }
                }
            }
        }

        // ---- flush per-class accumulators ----
        const int dbase = lane * 4;
        atomicAdd(&g_sums[(base + 0) * D + dbase + 0], a0.x);
        atomicAdd(&g_sums[(base + 0) * D + dbase + 1], a0.y);
        atomicAdd(&g_sums[(base + 0) * D + dbase + 2], a0.z);
        atomicAdd(&g_sums[(base + 0) * D + dbase + 3], a0.w);
        atomicAdd(&g_sums[(base + 1) * D + dbase + 0], a1.x);
        atomicAdd(&g_sums[(base + 1) * D + dbase + 1], a1.y);
        atomicAdd(&g_sums[(base + 1) * D + dbase + 2], a1.z);
        atomicAdd(&g_sums[(base + 1) * D + dbase + 3], a1.w);
        atomicAdd(&g_sums[(base + 2) * D + dbase + 0], a2.x);
        atomicAdd(&g_sums[(base + 2) * D + dbase + 1], a2.y);
        atomicAdd(&g_sums[(base + 2) * D + dbase + 2], a2.z);
        atomicAdd(&g_sums[(base + 2) * D + dbase + 3], a2.w);
        atomicAdd(&g_sums[(base + 3) * D + dbase + 0], a3.x);
        atomicAdd(&g_sums[(base + 3) * D + dbase + 1], a3.y);
        atomicAdd(&g_sums[(base + 3) * D + dbase + 2], a3.z);
        atomicAdd(&g_sums[(base + 3) * D + dbase + 3], a3.w);
        if (lane == 0) {
            atomicAdd(&g_counts[base + 0], c0);
            atomicAdd(&g_counts[base + 1], c1);
            atomicAdd(&g_counts[base + 2], c2);
            atomicAdd(&g_counts[base + 3], c3);
        }
    } else {
        // ================= CE role (98 blocks) =================
        const float4* lg4 = (const float4*)logits;
        const int cid = blockIdx.x / 3;           // 0..97
        const int nct = (N + 255) / 256;
        const int hw  = wid * 2 + half;           // 0..31 half-warps

        for (int t = cid; t < nct; t += NCE) {
            const int rb = t * 256 + hw * 8;      // 8 consecutive rows per half-warp
            float4 v[8]; float gt[8];
            unsigned ok = 0;
            #pragma unroll
            for (int u = 0; u < 8; ++u) {
                int r = rb + u;
                if (r < N) {
                    v[u]  = lg4[(unsigned)(r * (C / 4) + hl)];
                    int l = (int)lab_w[(unsigned)(r << lsh)];
                    gt[u] = logits[(unsigned)(r * C + l)];   // bcast, L1-hit
                    ok |= (1u << u);
                } else {
                    v[u] = make_float4(0.f, 0.f, 0.f, 0.f);
                    gt[u] = 0.0f;
                }
            }
            float e[8];
            #pragma unroll
            for (int u = 0; u < 8; ++u)
                e[u] = __expf(v[u].x) + __expf(v[u].y)
                     + __expf(v[u].z) + __expf(v[u].w);
            #pragma unroll
            for (int o = 8; o; o >>= 1) {
                #pragma unroll
                for (int u = 0; u < 8; ++u)
                    e[u] += __shfl_xor_sync(0xffffffffu, e[u], o);
            }
            if (hl == 0) {
                #pragma unroll
                for (int u = 0; u < 8; ++u)
                    if ((ok >> u) & 1u) ce_acc += __logf(e[u]) - gt[u];
            }
        }
    }

    // ---- common tail: block CE reduce + completion mark ----
    ce_acc += __shfl_xor_sync(0xffffffffu, ce_acc, 16);
    if (lane == 0) s_red[wid] = ce_acc;
    __syncthreads();
    if (tid == 0) {
        float s = 0.0f;
        #pragma unroll
        for (int i = 0; i < THREADS_MAIN / 32; ++i) s += s_red[i];
        atomicAdd(&g_ce, s);
        __threadfence();
        s_rank = atomicAdd(&g_done, 1u);
    }
    __syncthreads();

    // =========== last block: finalize + re-zero scratch ===========
    if (s_rank == GRID_MAIN - 1) {
        __threadfence();  // see all blocks' atomics

        #pragma unroll
        for (int cc = 0; cc < 4; ++cc) {
            int c = base + cc;
            float4 vv = ((const float4*)(g_sums + c * D))[lane];
            float dot = vv.x*vv.x + vv.y*vv.y + vv.z*vv.z + vv.w*vv.w;
            #pragma unroll
            for (int o = 16; o; o >>= 1)
                dot += __shfl_xor_sync(0xffffffffu, dot, o);
            if (lane == 0) {
                float cnt  = g_counts[c];
                float safe = fmaxf(cnt, 1.0f);
                // sum ||z||^2 == cnt (z unit-norm), so ssd = cnt - ||sum z||^2 / n
                float ssd  = cnt - dot / safe;
                bool valid = (cnt > 1.0f);
                s_pc[c]     = valid ? (ssd / safe) : 0.0f;
                s_pc[C + c] = valid ? 1.0f : 0.0f;
            }
        }
        __syncthreads();
        if (tid == 0) {
            float sp = 0.0f, nv = 0.0f;
            #pragma unroll
            for (int c = 0; c < C; ++c) { sp += s_pc[c]; nv += s_pc[C + c]; }
            float proto = sp / fmaxf(nv, 1.0f);
            float ce    = g_ce / (float)N;
            out[0] = (1.0f - LAMBDA_PROTO) * ce + LAMBDA_PROTO * proto;
        }

        // re-zero scratch for next graph replay
        for (int i = tid; i < C * D; i += THREADS_MAIN) g_sums[i] = 0.0f;
        if (tid < C) g_counts[tid] = 0.0f;
        if (tid == 0) { g_ce = 0.0f; __threadfence(); g_done = 0u; }
    }
}

// ---------------------------------------------------------
extern "C" void kernel_launch(void* const* d_in, const int* in_sizes, int n_in,
                              void* d_out, int out_size) {
    const float* emb          = (const float*)d_in[0];
    const float* logits       = (const float*)d_in[1];
    const unsigned int* lab_w = (const unsigned int*)d_in[2];
    int N = in_sizes[2];

    fused_kernel<<<GRID_MAIN, THREADS_MAIN>>>(emb, logits, lab_w, N, (float*)d_out);
}